// round 1
// baseline (speedup 1.0000x reference)
#include <cuda_runtime.h>
#include <cuda_bf16.h>
#include <math.h>

// Problem constants
#define B_    32
#define H_    1024
#define NH_   16
#define HD_   64
#define BS_   16
#define MAXKV 2048
#define BPS_  128                      // blocks per sequence
#define NB_   4096                     // physical blocks
#define SPLITS 8
#define TOKS_PER_SPLIT 256             // MAXKV / SPLITS
#define SCALE_ 0.125f                  // HD^-0.5
#define VOFF_ ((size_t)NB_ * BS_ * NH_ * HD_)   // offset of value cache

// Scratch (device globals: no allocation allowed)
__device__ float g_q[B_ * H_];
__device__ float g_attn[B_ * H_];
__device__ float g_pm[B_ * NH_ * SPLITS];
__device__ float g_pl[B_ * NH_ * SPLITS];
__device__ float g_po[(size_t)B_ * NH_ * SPLITS * HD_];

// ---------------------------------------------------------------------------
// GEMM: Y[b, j] = sum_k X[b,k] * W[k*ldw + j] + bias[j]
// X: [Btot, 1024] contiguous. Block: 64 cols x 8 batches. blockDim = 256.
// grid = (N/64, Btot/8)
// ---------------------------------------------------------------------------
__global__ __launch_bounds__(256) void gemm_kernel(
    const float* __restrict__ X, const float* __restrict__ W,
    const float* __restrict__ bias, float* __restrict__ Y, int ldw)
{
    __shared__ float xs[8 * 1024];   // 32 KB
    const int tid = threadIdx.x;
    const int bb  = blockIdx.y * 8;

    // load 8 rows of X (contiguous) into smem
    #pragma unroll
    for (int i = tid; i < 8 * 1024; i += 256)
        xs[i] = X[bb * 1024 + i];
    __syncthreads();

    const int col = blockIdx.x * 64 + (tid & 63);
    const int bg  = tid >> 6;                 // 0..3 -> handles 2 batches
    const float* __restrict__ wp = W + col;
    const float* __restrict__ x0 = xs + (bg * 2) * 1024;
    const float* __restrict__ x1 = x0 + 1024;

    float acc0 = 0.f, acc1 = 0.f;
    #pragma unroll 4
    for (int k = 0; k < 1024; k++) {
        float wv = wp[(size_t)k * ldw];
        acc0 = fmaf(x0[k], wv, acc0);
        acc1 = fmaf(x1[k], wv, acc1);
    }
    float bv = bias[col];
    Y[(bb + bg * 2    ) * 1024 + col] = acc0 + bv;
    Y[(bb + bg * 2 + 1) * 1024 + col] = acc1 + bv;
}

// ---------------------------------------------------------------------------
// Paged attention, split-KV flash decode.
// grid = (NH, SPLITS, B), block = 128 threads (4 warps), 1 warp per token.
// ---------------------------------------------------------------------------
__global__ __launch_bounds__(128) void attn_kernel(
    const float* __restrict__ kv, const int* __restrict__ bt,
    const int* __restrict__ seq_lens)
{
    const int h     = blockIdx.x;
    const int split = blockIdx.y;
    const int b     = blockIdx.z;
    const int tid   = threadIdx.x;
    const int w     = tid >> 5;
    const int lane  = tid & 31;

    const int seq   = seq_lens[b];
    const int start = split * TOKS_PER_SPLIT;
    const int idx   = (b * NH_ + h) * SPLITS + split;

    if (start >= seq) {
        if (tid == 0) g_pl[idx] = 0.f;
        return;
    }
    const int n = min(TOKS_PER_SPLIT, seq - start);

    __shared__ int   sbt[16];
    __shared__ float sm[4], sl[4];
    __shared__ float so[4][HD_];

    if (tid < 16) sbt[tid] = bt[b * BPS_ + split * 16 + tid];
    __syncthreads();

    // q for this (b, h): float2 per lane
    const float2 q2 = *reinterpret_cast<const float2*>(
        &g_q[b * H_ + h * HD_ + lane * 2]);

    float m = -INFINITY, l = 0.f;
    float2 acc = make_float2(0.f, 0.f);

    for (int tl = w; tl < n; tl += 4) {
        const int phys = sbt[tl >> 4];
        const int pos  = tl & 15;
        const size_t base = ((size_t)(phys * BS_ + pos) * NH_ + h) * HD_;

        const float2 k2 = reinterpret_cast<const float2*>(kv + base)[lane];
        float s = q2.x * k2.x + q2.y * k2.y;
        #pragma unroll
        for (int off = 16; off; off >>= 1)
            s += __shfl_xor_sync(0xffffffffu, s, off);
        s *= SCALE_;

        const float2 v2 = reinterpret_cast<const float2*>(kv + VOFF_ + base)[lane];

        const float mn    = fmaxf(m, s);
        const float alpha = __expf(m - mn);   // 0 on first iter (m = -inf)
        const float p     = __expf(s - mn);
        l     = l * alpha + p;
        acc.x = fmaf(acc.x, alpha, p * v2.x);
        acc.y = fmaf(acc.y, alpha, p * v2.y);
        m     = mn;
    }

    if (lane == 0) { sm[w] = m; sl[w] = l; }
    so[w][lane * 2]     = acc.x;
    so[w][lane * 2 + 1] = acc.y;
    __syncthreads();

    if (tid < HD_) {
        const float M = fmaxf(fmaxf(sm[0], sm[1]), fmaxf(sm[2], sm[3]));
        float L = 0.f, O = 0.f;
        #pragma unroll
        for (int ww = 0; ww < 4; ww++) {
            const float wt = __expf(sm[ww] - M);  // 0 for empty warps
            L += wt * sl[ww];
            O += wt * so[ww][tid];
        }
        g_po[(size_t)idx * HD_ + tid] = O;
        if (tid == 0) { g_pm[idx] = M; g_pl[idx] = L; }
    }
}

// ---------------------------------------------------------------------------
// Combine split-KV partials. grid = B*NH, block = 64.
// ---------------------------------------------------------------------------
__global__ __launch_bounds__(64) void combine_kernel()
{
    const int bh = blockIdx.x;
    const int d  = threadIdx.x;

    float M = -INFINITY;
    #pragma unroll
    for (int s = 0; s < SPLITS; s++) {
        const float ls = g_pl[bh * SPLITS + s];
        if (ls > 0.f) M = fmaxf(M, g_pm[bh * SPLITS + s]);
    }
    float L = 0.f, O = 0.f;
    #pragma unroll
    for (int s = 0; s < SPLITS; s++) {
        const float ls = g_pl[bh * SPLITS + s];
        if (ls > 0.f) {
            const float wt = __expf(g_pm[bh * SPLITS + s] - M);
            L += wt * ls;
            O += wt * g_po[(size_t)(bh * SPLITS + s) * HD_ + d];
        }
    }
    g_attn[bh * HD_ + d] = O / L;
}

// ---------------------------------------------------------------------------
extern "C" void kernel_launch(void* const* d_in, const int* in_sizes, int n_in,
                              void* d_out, int out_size)
{
    const float* hs     = (const float*)d_in[0];  // [32,1,1024]
    const float* kv     = (const float*)d_in[1];  // [2,4096,16,16,64]
    const int*   bt     = (const int*)  d_in[2];  // [32,128]
    const int*   sl     = (const int*)  d_in[3];  // [32]
    const float* w_attn = (const float*)d_in[4];  // [1024,3072]
    const float* b_attn = (const float*)d_in[5];  // [3072]
    const float* w_proj = (const float*)d_in[6];  // [1024,1024]
    const float* b_proj = (const float*)d_in[7];  // [1024]
    float*       out    = (float*)d_out;          // [32,1,1024]

    void *qp, *ap;
    cudaGetSymbolAddress(&qp, g_q);
    cudaGetSymbolAddress(&ap, g_attn);

    // q = hs @ w_attn[:, :1024] + b_attn[:1024]
    gemm_kernel<<<dim3(16, 4), 256>>>(hs, w_attn, b_attn, (float*)qp, 3072);

    // split-KV paged flash decode
    attn_kernel<<<dim3(NH_, SPLITS, B_), 128>>>(kv, bt, sl);

    // combine partials
    combine_kernel<<<B_ * NH_, 64>>>();

    // out = attn @ w_proj + b_proj
    gemm_kernel<<<dim3(16, 4), 256>>>((const float*)ap, w_proj, b_proj, out, 1024);
}

// round 2
// speedup vs baseline: 3.0999x; 3.0999x over previous
#include <cuda_runtime.h>
#include <cuda_bf16.h>
#include <math.h>

// Problem constants
#define B_    32
#define H_    1024
#define NH_   16
#define HD_   64
#define BS_   16
#define MAXKV 2048
#define BPS_  128                      // blocks per sequence
#define NB_   4096                     // physical blocks
#define SPLITS 8
#define TOKS_PER_SPLIT 256             // MAXKV / SPLITS
#define SCALE_ 0.125f                  // HD^-0.5
#define VOFF_ ((size_t)NB_ * BS_ * NH_ * HD_)   // offset of value cache

#define KS_   16                       // GEMM k-splits
#define KCH_  64                       // k per split (KS_*KCH_ = 1024)

// Scratch (device globals: no allocation allowed)
__device__ float g_q[B_ * H_];
__device__ float g_attn[B_ * H_];
__device__ float g_pm[B_ * NH_ * SPLITS];
__device__ float g_pl[B_ * NH_ * SPLITS];
__device__ float g_po[(size_t)B_ * NH_ * SPLITS * HD_];
__device__ float g_part[KS_ * B_ * H_];   // 2 MB GEMM partials

// ---------------------------------------------------------------------------
// Split-K GEMM stage 1: partial[ky][b][col] = sum_{k in chunk} X[b,k]*W[k,col]
// grid = (16 col-tiles, KS_), block = 256 (64 cols x 4 batch-groups of 8).
// W streamed exactly once, fully coalesced, 64 independent loads/thread.
// ---------------------------------------------------------------------------
__global__ __launch_bounds__(256) void gemm_part_kernel(
    const float* __restrict__ X, const float* __restrict__ W, int ldw)
{
    __shared__ float xs[KCH_][B_];     // xs[kk][b], 8 KB

    const int tid = threadIdx.x;
    const int k0  = blockIdx.y * KCH_;

    // load X tile [32 batches x 64 k] transposed into smem
    #pragma unroll
    for (int i = tid; i < B_ * KCH_; i += 256) {
        const int b  = i >> 6;          // i / KCH_
        const int kk = i & (KCH_ - 1);
        xs[kk][b] = X[b * H_ + k0 + kk];
    }
    __syncthreads();

    const int col = blockIdx.x * 64 + (tid & 63);
    const int b0  = (tid >> 6) * 8;     // batch group: 8 batches
    const float* __restrict__ wp = W + (size_t)k0 * ldw + col;

    float acc[8];
    #pragma unroll
    for (int j = 0; j < 8; j++) acc[j] = 0.f;

    #pragma unroll 8
    for (int kk = 0; kk < KCH_; kk++) {
        const float wv = wp[(size_t)kk * ldw];
        #pragma unroll
        for (int j = 0; j < 8; j++)
            acc[j] = fmaf(xs[kk][b0 + j], wv, acc[j]);
    }

    float* __restrict__ dst = g_part + ((size_t)blockIdx.y * B_) * H_ + col;
    #pragma unroll
    for (int j = 0; j < 8; j++)
        dst[(b0 + j) * H_] = acc[j];
}

// ---------------------------------------------------------------------------
// Split-K GEMM stage 2: Y[b][col] = bias[col] + sum_ky partial[ky][b][col]
// grid = 128, block = 256.
// ---------------------------------------------------------------------------
__global__ __launch_bounds__(256) void gemm_reduce_kernel(
    const float* __restrict__ bias, float* __restrict__ Y)
{
    const int i   = blockIdx.x * 256 + threadIdx.x;   // i in [0, 32*1024)
    const int col = i & (H_ - 1);

    float acc = bias[col];
    #pragma unroll
    for (int ky = 0; ky < KS_; ky++)
        acc += g_part[(size_t)ky * B_ * H_ + i];
    Y[i] = acc;
}

// ---------------------------------------------------------------------------
// Paged attention, split-KV flash decode.
// grid = (NH, SPLITS, B), block = 128 threads (4 warps), 1 warp per token.
// ---------------------------------------------------------------------------
__global__ __launch_bounds__(128) void attn_kernel(
    const float* __restrict__ kv, const int* __restrict__ bt,
    const int* __restrict__ seq_lens)
{
    const int h     = blockIdx.x;
    const int split = blockIdx.y;
    const int b     = blockIdx.z;
    const int tid   = threadIdx.x;
    const int w     = tid >> 5;
    const int lane  = tid & 31;

    const int seq   = seq_lens[b];
    const int start = split * TOKS_PER_SPLIT;
    const int idx   = (b * NH_ + h) * SPLITS + split;

    if (start >= seq) {
        if (tid == 0) g_pl[idx] = 0.f;
        return;
    }
    const int n = min(TOKS_PER_SPLIT, seq - start);

    __shared__ int   sbt[16];
    __shared__ float sm[4], sl[4];
    __shared__ float so[4][HD_];

    if (tid < 16) sbt[tid] = bt[b * BPS_ + split * 16 + tid];
    __syncthreads();

    // q for this (b, h): float2 per lane
    const float2 q2 = *reinterpret_cast<const float2*>(
        &g_q[b * H_ + h * HD_ + lane * 2]);

    float m = -INFINITY, l = 0.f;
    float2 acc = make_float2(0.f, 0.f);

    for (int tl = w; tl < n; tl += 4) {
        const int phys = sbt[tl >> 4];
        const int pos  = tl & 15;
        const size_t base = ((size_t)(phys * BS_ + pos) * NH_ + h) * HD_;

        const float2 k2 = reinterpret_cast<const float2*>(kv + base)[lane];
        float s = q2.x * k2.x + q2.y * k2.y;
        #pragma unroll
        for (int off = 16; off; off >>= 1)
            s += __shfl_xor_sync(0xffffffffu, s, off);
        s *= SCALE_;

        const float2 v2 = reinterpret_cast<const float2*>(kv + VOFF_ + base)[lane];

        const float mn    = fmaxf(m, s);
        const float alpha = __expf(m - mn);   // 0 on first iter (m = -inf)
        const float p     = __expf(s - mn);
        l     = l * alpha + p;
        acc.x = fmaf(acc.x, alpha, p * v2.x);
        acc.y = fmaf(acc.y, alpha, p * v2.y);
        m     = mn;
    }

    if (lane == 0) { sm[w] = m; sl[w] = l; }
    so[w][lane * 2]     = acc.x;
    so[w][lane * 2 + 1] = acc.y;
    __syncthreads();

    if (tid < HD_) {
        const float M = fmaxf(fmaxf(sm[0], sm[1]), fmaxf(sm[2], sm[3]));
        float L = 0.f, O = 0.f;
        #pragma unroll
        for (int ww = 0; ww < 4; ww++) {
            const float wt = __expf(sm[ww] - M);  // 0 for empty warps
            L += wt * sl[ww];
            O += wt * so[ww][tid];
        }
        g_po[(size_t)idx * HD_ + tid] = O;
        if (tid == 0) { g_pm[idx] = M; g_pl[idx] = L; }
    }
}

// ---------------------------------------------------------------------------
// Combine split-KV partials. grid = B*NH, block = 64.
// ---------------------------------------------------------------------------
__global__ __launch_bounds__(64) void combine_kernel()
{
    const int bh = blockIdx.x;
    const int d  = threadIdx.x;

    float M = -INFINITY;
    #pragma unroll
    for (int s = 0; s < SPLITS; s++) {
        const float ls = g_pl[bh * SPLITS + s];
        if (ls > 0.f) M = fmaxf(M, g_pm[bh * SPLITS + s]);
    }
    float L = 0.f, O = 0.f;
    #pragma unroll
    for (int s = 0; s < SPLITS; s++) {
        const float ls = g_pl[bh * SPLITS + s];
        if (ls > 0.f) {
            const float wt = __expf(g_pm[bh * SPLITS + s] - M);
            L += wt * ls;
            O += wt * g_po[(size_t)(bh * SPLITS + s) * HD_ + d];
        }
    }
    g_attn[bh * HD_ + d] = O / L;
}

// ---------------------------------------------------------------------------
extern "C" void kernel_launch(void* const* d_in, const int* in_sizes, int n_in,
                              void* d_out, int out_size)
{
    const float* hs     = (const float*)d_in[0];  // [32,1,1024]
    const float* kv     = (const float*)d_in[1];  // [2,4096,16,16,64]
    const int*   bt     = (const int*)  d_in[2];  // [32,128]
    const int*   sl     = (const int*)  d_in[3];  // [32]
    const float* w_attn = (const float*)d_in[4];  // [1024,3072]
    const float* b_attn = (const float*)d_in[5];  // [3072]
    const float* w_proj = (const float*)d_in[6];  // [1024,1024]
    const float* b_proj = (const float*)d_in[7];  // [1024]
    float*       out    = (float*)d_out;          // [32,1,1024]

    void *qp, *ap;
    cudaGetSymbolAddress(&qp, g_q);
    cudaGetSymbolAddress(&ap, g_attn);

    // q = hs @ w_attn[:, :1024] + b_attn[:1024]   (split-K, 2 stages)
    gemm_part_kernel<<<dim3(16, KS_), 256>>>(hs, w_attn, 3072);
    gemm_reduce_kernel<<<128, 256>>>(b_attn, (float*)qp);

    // split-KV paged flash decode
    attn_kernel<<<dim3(NH_, SPLITS, B_), 128>>>(kv, bt, sl);

    // combine partials
    combine_kernel<<<B_ * NH_, 64>>>();

    // out = attn @ w_proj + b_proj   (split-K, 2 stages)
    gemm_part_kernel<<<dim3(16, KS_), 256>>>((const float*)ap, w_proj, 1024);
    gemm_reduce_kernel<<<128, 256>>>(b_proj, out);
}

// round 3
// speedup vs baseline: 3.2860x; 1.0600x over previous
#include <cuda_runtime.h>
#include <cuda_bf16.h>
#include <math.h>

// Problem constants
#define B_    32
#define H_    1024
#define NH_   16
#define HD_   64
#define BS_   16
#define MAXKV 2048
#define BPS_  128                      // blocks per sequence
#define NB_   4096                     // physical blocks
#define SPLITS 8
#define TOKS_PER_SPLIT 256             // MAXKV / SPLITS
#define SCALE_ 0.125f                  // HD^-0.5
#define VOFF_ ((size_t)NB_ * BS_ * NH_ * HD_)   // offset of value cache

#define KS_   16                       // GEMM k-splits
#define KCH_  64                       // k per split (KS_*KCH_ = 1024)

// Scratch (device globals: no allocation allowed)
__device__ float g_attn[B_ * H_];
__device__ float g_pm[B_ * NH_ * SPLITS];
__device__ float g_pl[B_ * NH_ * SPLITS];
__device__ float g_po[(size_t)B_ * NH_ * SPLITS * HD_];
__device__ float g_part[KS_ * B_ * H_];   // 2 MB GEMM partials

// ---------------------------------------------------------------------------
// Split-K GEMM stage 1: partial[ky][b][col] = sum_{k in chunk} X[b,k]*W[k,col]
// grid = (16 col-tiles, KS_), block = 256 (64 cols x 4 batch-groups of 8).
// ---------------------------------------------------------------------------
__global__ __launch_bounds__(256) void gemm_part_kernel(
    const float* __restrict__ X, const float* __restrict__ W, int ldw)
{
    __shared__ float xs[KCH_][B_];     // xs[kk][b], 8 KB

    const int tid = threadIdx.x;
    const int k0  = blockIdx.y * KCH_;

    #pragma unroll
    for (int i = tid; i < B_ * KCH_; i += 256) {
        const int b  = i >> 6;
        const int kk = i & (KCH_ - 1);
        xs[kk][b] = X[b * H_ + k0 + kk];
    }
    __syncthreads();

    const int col = blockIdx.x * 64 + (tid & 63);
    const int b0  = (tid >> 6) * 8;
    const float* __restrict__ wp = W + (size_t)k0 * ldw + col;

    float acc[8];
    #pragma unroll
    for (int j = 0; j < 8; j++) acc[j] = 0.f;

    #pragma unroll 16
    for (int kk = 0; kk < KCH_; kk++) {
        const float wv = wp[(size_t)kk * ldw];
        #pragma unroll
        for (int j = 0; j < 8; j++)
            acc[j] = fmaf(xs[kk][b0 + j], wv, acc[j]);
    }

    float* __restrict__ dst = g_part + ((size_t)blockIdx.y * B_) * H_ + col;
    #pragma unroll
    for (int j = 0; j < 8; j++)
        dst[(b0 + j) * H_] = acc[j];
}

// ---------------------------------------------------------------------------
// Split-K GEMM stage 2: Y[b][col] = bias[col] + sum_ky partial[ky][b][col]
// ---------------------------------------------------------------------------
__global__ __launch_bounds__(256) void gemm_reduce_kernel(
    const float* __restrict__ bias, float* __restrict__ Y)
{
    const int i   = blockIdx.x * 256 + threadIdx.x;
    const int col = i & (H_ - 1);

    float acc = bias[col];
    #pragma unroll
    for (int ky = 0; ky < KS_; ky++)
        acc += g_part[(size_t)ky * B_ * H_ + i];
    Y[i] = acc;
}

// ---------------------------------------------------------------------------
// Paged attention, split-KV flash decode, q split-K reduce fused in prologue.
// grid = (NH, SPLITS, B), block = 128 (4 warps). 2 tokens per warp-iteration
// (16-lane groups, float4 over HD), double-buffered K and V loads.
// ---------------------------------------------------------------------------
__global__ __launch_bounds__(128) void attn_kernel(
    const float* __restrict__ kv, const int* __restrict__ bt,
    const int* __restrict__ seq_lens, const float* __restrict__ b_attn)
{
    const int h     = blockIdx.x;
    const int split = blockIdx.y;
    const int b     = blockIdx.z;
    const int tid   = threadIdx.x;
    const int w     = tid >> 5;
    const int lane  = tid & 31;

    const int seq   = seq_lens[b];
    const int start = split * TOKS_PER_SPLIT;
    const int idx   = (b * NH_ + h) * SPLITS + split;

    if (start >= seq) {
        if (tid == 0) g_pl[idx] = 0.f;
        return;
    }
    const int n = min(TOKS_PER_SPLIT, seq - start);

    __shared__ int   sbt[16];
    __shared__ float sq[HD_];
    __shared__ float smm[8], sll[8];
    __shared__ float so[8][HD_];

    if (tid < 16) sbt[tid] = bt[b * BPS_ + split * 16 + tid];
    if (tid < HD_) {
        // fused q reduce: q[b, h*64+tid] = bias + sum over k-splits
        float acc = b_attn[h * HD_ + tid];
        #pragma unroll
        for (int ky = 0; ky < KS_; ky++)
            acc += g_part[(size_t)ky * B_ * H_ + b * H_ + h * HD_ + tid];
        sq[tid] = acc;
    }
    __syncthreads();

    const int g    = lane >> 4;     // which token of the pair
    const int l16  = lane & 15;     // lane within 16-lane group
    const float4 q4 = *reinterpret_cast<const float4*>(sq + l16 * 4);

    float  m = -INFINITY, l = 0.f;
    float4 acc = make_float4(0.f, 0.f, 0.f, 0.f);

    int tbase = w * 2;              // group token = tbase + g, stride 8

    float4 k4, v4;
    {
        const int t = tbase + g;
        if (t < n) {
            const int phys = sbt[t >> 4];
            const size_t ba = ((size_t)(phys * BS_ + (t & 15)) * NH_ + h) * HD_ + l16 * 4;
            k4 = *reinterpret_cast<const float4*>(kv + ba);
            v4 = *reinterpret_cast<const float4*>(kv + VOFF_ + ba);
        }
    }

    while (tbase < n) {
        const int tnb = tbase + 8;
        float4 k4n, v4n;
        {
            const int t = tnb + g;
            if (t < n) {
                const int phys = sbt[t >> 4];
                const size_t ba = ((size_t)(phys * BS_ + (t & 15)) * NH_ + h) * HD_ + l16 * 4;
                k4n = *reinterpret_cast<const float4*>(kv + ba);
                v4n = *reinterpret_cast<const float4*>(kv + VOFF_ + ba);
            }
        }

        float s = q4.x * k4.x + q4.y * k4.y + q4.z * k4.z + q4.w * k4.w;
        s += __shfl_xor_sync(0xffffffffu, s, 8);
        s += __shfl_xor_sync(0xffffffffu, s, 4);
        s += __shfl_xor_sync(0xffffffffu, s, 2);
        s += __shfl_xor_sync(0xffffffffu, s, 1);
        s *= SCALE_;

        if (tbase + g < n) {
            const float mn    = fmaxf(m, s);
            const float alpha = __expf(m - mn);
            const float p     = __expf(s - mn);
            l     = l * alpha + p;
            acc.x = fmaf(acc.x, alpha, p * v4.x);
            acc.y = fmaf(acc.y, alpha, p * v4.y);
            acc.z = fmaf(acc.z, alpha, p * v4.z);
            acc.w = fmaf(acc.w, alpha, p * v4.w);
            m     = mn;
        }
        k4 = k4n; v4 = v4n;
        tbase = tnb;
    }

    const int slot = w * 2 + g;
    if (l16 == 0) { smm[slot] = m; sll[slot] = l; }
    *reinterpret_cast<float4*>(&so[slot][l16 * 4]) = acc;
    __syncthreads();

    if (tid < HD_) {
        float M = -INFINITY;
        #pragma unroll
        for (int ww = 0; ww < 8; ww++) M = fmaxf(M, smm[ww]);
        float L = 0.f, O = 0.f;
        #pragma unroll
        for (int ww = 0; ww < 8; ww++) {
            const float wt = __expf(smm[ww] - M);  // 0 for empty slots (m=-inf)
            L += wt * sll[ww];
            O += wt * so[ww][tid];
        }
        g_po[(size_t)idx * HD_ + tid] = O;
        if (tid == 0) { g_pm[idx] = M; g_pl[idx] = L; }
    }
}

// ---------------------------------------------------------------------------
// Combine split-KV partials. grid = 128, block = 64 (4 bh per block,
// 16 threads per bh, float4 over d). Writes g_attn.
// ---------------------------------------------------------------------------
__global__ __launch_bounds__(64) void combine_kernel()
{
    const int t   = threadIdx.x;
    const int bh  = blockIdx.x * 4 + (t >> 4);
    const int d4  = (t & 15) * 4;

    float pm[SPLITS], pl[SPLITS];
    #pragma unroll
    for (int s = 0; s < SPLITS; s++) {
        pm[s] = g_pm[bh * SPLITS + s];
        pl[s] = g_pl[bh * SPLITS + s];
    }

    float M = -INFINITY;
    #pragma unroll
    for (int s = 0; s < SPLITS; s++)
        if (pl[s] > 0.f) M = fmaxf(M, pm[s]);

    float wt[SPLITS];
    #pragma unroll
    for (int s = 0; s < SPLITS; s++)
        wt[s] = (pl[s] > 0.f) ? __expf(pm[s] - M) : 0.f;

    float L = 0.f;
    float4 O = make_float4(0.f, 0.f, 0.f, 0.f);
    #pragma unroll
    for (int s = 0; s < SPLITS; s++) {
        const float4 po = *reinterpret_cast<const float4*>(
            g_po + (size_t)(bh * SPLITS + s) * HD_ + d4);
        L  += wt[s] * pl[s];
        O.x = fmaf(wt[s], po.x, O.x);
        O.y = fmaf(wt[s], po.y, O.y);
        O.z = fmaf(wt[s], po.z, O.z);
        O.w = fmaf(wt[s], po.w, O.w);
    }
    const float inv = 1.f / L;
    float4 r = make_float4(O.x * inv, O.y * inv, O.z * inv, O.w * inv);
    *reinterpret_cast<float4*>(g_attn + bh * HD_ + d4) = r;
}

// ---------------------------------------------------------------------------
extern "C" void kernel_launch(void* const* d_in, const int* in_sizes, int n_in,
                              void* d_out, int out_size)
{
    const float* hs     = (const float*)d_in[0];  // [32,1,1024]
    const float* kv     = (const float*)d_in[1];  // [2,4096,16,16,64]
    const int*   bt     = (const int*)  d_in[2];  // [32,128]
    const int*   sl     = (const int*)  d_in[3];  // [32]
    const float* w_attn = (const float*)d_in[4];  // [1024,3072]
    const float* b_attn = (const float*)d_in[5];  // [3072]
    const float* w_proj = (const float*)d_in[6];  // [1024,1024]
    const float* b_proj = (const float*)d_in[7];  // [1024]
    float*       out    = (float*)d_out;          // [32,1,1024]

    void* ap;
    cudaGetSymbolAddress(&ap, g_attn);

    // q partials: hs @ w_attn[:, :1024]
    gemm_part_kernel<<<dim3(16, KS_), 256>>>(hs, w_attn, 3072);

    // split-KV paged flash decode (q reduce + bias fused in prologue)
    attn_kernel<<<dim3(NH_, SPLITS, B_), 128>>>(kv, bt, sl, b_attn);

    // combine partials -> g_attn
    combine_kernel<<<128, 64>>>();

    // out = g_attn @ w_proj + b_proj
    gemm_part_kernel<<<dim3(16, KS_), 256>>>((const float*)ap, w_proj, 1024);
    gemm_reduce_kernel<<<128, 256>>>(b_proj, out);
}

// round 6
// speedup vs baseline: 3.6097x; 1.0985x over previous
#include <cuda_runtime.h>
#include <cuda_bf16.h>
#include <math.h>

// Problem constants
#define B_    32
#define H_    1024
#define NH_   16
#define HD_   64
#define BS_   16
#define MAXKV 2048
#define BPS_  128                      // blocks per sequence
#define NB_   4096                     // physical blocks
#define SPLITS 8
#define TOKS_PER_SPLIT 256             // MAXKV / SPLITS
#define SCALE_ 0.125f                  // HD^-0.5
#define VOFF_ ((size_t)NB_ * BS_ * NH_ * HD_)   // offset of value cache

#define KS_   32                       // GEMM k-splits
#define KCH_  32                       // k per split (KS_*KCH_ = 1024)

// Scratch (device globals: no allocation allowed)
__device__ float g_attn[B_ * H_];
__device__ float g_pm[B_ * NH_ * SPLITS];
__device__ float g_pl[B_ * NH_ * SPLITS];
__device__ float g_po[(size_t)B_ * NH_ * SPLITS * HD_];
__device__ float g_part[KS_ * B_ * H_];   // 4 MB GEMM partials

// ---------------------------------------------------------------------------
// Split-K GEMM stage 1: partial[ky][b][col] = sum_{k in chunk} X[b,k]*W[k,col]
// grid = (16 col-tiles, KS_=32) = 512 blocks, block = 256
// (64 cols x 4 batch-groups of 8). Inner loop: 1 LDG + 2 LDS.128 + 8 FMA.
// ---------------------------------------------------------------------------
__global__ __launch_bounds__(256) void gemm_part_kernel(
    const float* __restrict__ X, const float* __restrict__ W, int ldw)
{
    __shared__ float xs[KCH_][B_];     // xs[kk][b], 4 KB

    const int tid = threadIdx.x;
    const int k0  = blockIdx.y * KCH_;

    // load X tile [32 batches x 32 k] transposed into smem
    #pragma unroll
    for (int i = tid; i < B_ * KCH_; i += 256) {
        const int b  = i >> 5;          // i / KCH_
        const int kk = i & (KCH_ - 1);
        xs[kk][b] = X[b * H_ + k0 + kk];
    }
    __syncthreads();

    const int col = blockIdx.x * 64 + (tid & 63);
    const int b0  = (tid >> 6) * 8;     // batch group: 8 batches
    const float* __restrict__ wp = W + (size_t)k0 * ldw + col;

    float acc[8];
    #pragma unroll
    for (int j = 0; j < 8; j++) acc[j] = 0.f;

    #pragma unroll 16
    for (int kk = 0; kk < KCH_; kk++) {
        const float wv = wp[(size_t)kk * ldw];
        const float4 xa = *reinterpret_cast<const float4*>(&xs[kk][b0]);
        const float4 xb = *reinterpret_cast<const float4*>(&xs[kk][b0 + 4]);
        acc[0] = fmaf(xa.x, wv, acc[0]);
        acc[1] = fmaf(xa.y, wv, acc[1]);
        acc[2] = fmaf(xa.z, wv, acc[2]);
        acc[3] = fmaf(xa.w, wv, acc[3]);
        acc[4] = fmaf(xb.x, wv, acc[4]);
        acc[5] = fmaf(xb.y, wv, acc[5]);
        acc[6] = fmaf(xb.z, wv, acc[6]);
        acc[7] = fmaf(xb.w, wv, acc[7]);
    }

    float* __restrict__ dst = g_part + ((size_t)blockIdx.y * B_) * H_ + col;
    #pragma unroll
    for (int j = 0; j < 8; j++)
        dst[(b0 + j) * H_] = acc[j];
}

// ---------------------------------------------------------------------------
// Split-K GEMM stage 2: Y[b][col] = bias[col] + sum_ky partial[ky][b][col]
// ---------------------------------------------------------------------------
__global__ __launch_bounds__(256) void gemm_reduce_kernel(
    const float* __restrict__ bias, float* __restrict__ Y)
{
    const int i   = blockIdx.x * 256 + threadIdx.x;
    const int col = i & (H_ - 1);

    float acc = bias[col];
    #pragma unroll
    for (int ky = 0; ky < KS_; ky++)
        acc += g_part[(size_t)ky * B_ * H_ + i];
    Y[i] = acc;
}

// ---------------------------------------------------------------------------
// Paged attention, split-KV flash decode, q split-K reduce fused in prologue.
// grid = (NH, SPLITS, B), block = 128 (4 warps). 2 tokens per warp-iteration
// (16-lane groups, float4 over HD), double-buffered K and V loads.
// ---------------------------------------------------------------------------
__global__ __launch_bounds__(128) void attn_kernel(
    const float* __restrict__ kv, const int* __restrict__ bt,
    const int* __restrict__ seq_lens, const float* __restrict__ b_attn)
{
    const int h     = blockIdx.x;
    const int split = blockIdx.y;
    const int b     = blockIdx.z;
    const int tid   = threadIdx.x;
    const int w     = tid >> 5;
    const int lane  = tid & 31;

    const int seq   = seq_lens[b];
    const int start = split * TOKS_PER_SPLIT;
    const int idx   = (b * NH_ + h) * SPLITS + split;

    if (start >= seq) {
        if (tid == 0) g_pl[idx] = 0.f;
        return;
    }
    const int n = min(TOKS_PER_SPLIT, seq - start);

    __shared__ int   sbt[16];
    __shared__ float sq[HD_];
    __shared__ float smm[8], sll[8];
    __shared__ float so[8][HD_];

    if (tid < 16) sbt[tid] = bt[b * BPS_ + split * 16 + tid];
    if (tid < HD_) {
        // fused q reduce: q[b, h*64+tid] = bias + sum over k-splits
        float acc = b_attn[h * HD_ + tid];
        #pragma unroll
        for (int ky = 0; ky < KS_; ky++)
            acc += g_part[(size_t)ky * B_ * H_ + b * H_ + h * HD_ + tid];
        sq[tid] = acc;
    }
    __syncthreads();

    const int g    = lane >> 4;     // which token of the pair
    const int l16  = lane & 15;     // lane within 16-lane group
    const float4 q4 = *reinterpret_cast<const float4*>(sq + l16 * 4);

    float  m = -INFINITY, l = 0.f;
    float4 acc = make_float4(0.f, 0.f, 0.f, 0.f);

    int tbase = w * 2;              // group token = tbase + g, stride 8

    float4 k4, v4;
    {
        const int t = tbase + g;
        if (t < n) {
            const int phys = sbt[t >> 4];
            const size_t ba = ((size_t)(phys * BS_ + (t & 15)) * NH_ + h) * HD_ + l16 * 4;
            k4 = *reinterpret_cast<const float4*>(kv + ba);
            v4 = *reinterpret_cast<const float4*>(kv + VOFF_ + ba);
        }
    }

    while (tbase < n) {
        const int tnb = tbase + 8;
        float4 k4n, v4n;
        {
            const int t = tnb + g;
            if (t < n) {
                const int phys = sbt[t >> 4];
                const size_t ba = ((size_t)(phys * BS_ + (t & 15)) * NH_ + h) * HD_ + l16 * 4;
                k4n = *reinterpret_cast<const float4*>(kv + ba);
                v4n = *reinterpret_cast<const float4*>(kv + VOFF_ + ba);
            }
        }

        float s = q4.x * k4.x + q4.y * k4.y + q4.z * k4.z + q4.w * k4.w;
        s += __shfl_xor_sync(0xffffffffu, s, 8);
        s += __shfl_xor_sync(0xffffffffu, s, 4);
        s += __shfl_xor_sync(0xffffffffu, s, 2);
        s += __shfl_xor_sync(0xffffffffu, s, 1);
        s *= SCALE_;

        if (tbase + g < n) {
            const float mn    = fmaxf(m, s);
            const float alpha = __expf(m - mn);
            const float p     = __expf(s - mn);
            l     = l * alpha + p;
            acc.x = fmaf(acc.x, alpha, p * v4.x);
            acc.y = fmaf(acc.y, alpha, p * v4.y);
            acc.z = fmaf(acc.z, alpha, p * v4.z);
            acc.w = fmaf(acc.w, alpha, p * v4.w);
            m     = mn;
        }
        k4 = k4n; v4 = v4n;
        tbase = tnb;
    }

    const int slot = w * 2 + g;
    if (l16 == 0) { smm[slot] = m; sll[slot] = l; }
    *reinterpret_cast<float4*>(&so[slot][l16 * 4]) = acc;
    __syncthreads();

    if (tid < HD_) {
        float M = -INFINITY;
        #pragma unroll
        for (int ww = 0; ww < 8; ww++) M = fmaxf(M, smm[ww]);
        float L = 0.f, O = 0.f;
        #pragma unroll
        for (int ww = 0; ww < 8; ww++) {
            const float wt = __expf(smm[ww] - M);  // 0 for empty slots (m=-inf)
            L += wt * sll[ww];
            O += wt * so[ww][tid];
        }
        g_po[(size_t)idx * HD_ + tid] = O;
        if (tid == 0) { g_pm[idx] = M; g_pl[idx] = L; }
    }
}

// ---------------------------------------------------------------------------
// Combine split-KV partials. grid = 128, block = 64 (4 bh per block,
// 16 threads per bh, float4 over d). Writes g_attn.
// ---------------------------------------------------------------------------
__global__ __launch_bounds__(64) void combine_kernel()
{
    const int t   = threadIdx.x;
    const int bh  = blockIdx.x * 4 + (t >> 4);
    const int d4  = (t & 15) * 4;

    float pm[SPLITS], pl[SPLITS];
    #pragma unroll
    for (int s = 0; s < SPLITS; s++) {
        pm[s] = g_pm[bh * SPLITS + s];
        pl[s] = g_pl[bh * SPLITS + s];
    }

    float M = -INFINITY;
    #pragma unroll
    for (int s = 0; s < SPLITS; s++)
        if (pl[s] > 0.f) M = fmaxf(M, pm[s]);

    float wt[SPLITS];
    #pragma unroll
    for (int s = 0; s < SPLITS; s++)
        wt[s] = (pl[s] > 0.f) ? __expf(pm[s] - M) : 0.f;

    float L = 0.f;
    float4 O = make_float4(0.f, 0.f, 0.f, 0.f);
    #pragma unroll
    for (int s = 0; s < SPLITS; s++) {
        const float4 po = *reinterpret_cast<const float4*>(
            g_po + (size_t)(bh * SPLITS + s) * HD_ + d4);
        L  += wt[s] * pl[s];
        O.x = fmaf(wt[s], po.x, O.x);
        O.y = fmaf(wt[s], po.y, O.y);
        O.z = fmaf(wt[s], po.z, O.z);
        O.w = fmaf(wt[s], po.w, O.w);
    }
    const float inv = 1.f / L;
    float4 r = make_float4(O.x * inv, O.y * inv, O.z * inv, O.w * inv);
    *reinterpret_cast<float4*>(g_attn + bh * HD_ + d4) = r;
}

// ---------------------------------------------------------------------------
extern "C" void kernel_launch(void* const* d_in, const int* in_sizes, int n_in,
                              void* d_out, int out_size)
{
    const float* hs     = (const float*)d_in[0];  // [32,1,1024]
    const float* kv     = (const float*)d_in[1];  // [2,4096,16,16,64]
    const int*   bt     = (const int*)  d_in[2];  // [32,128]
    const int*   sl     = (const int*)  d_in[3];  // [32]
    const float* w_attn = (const float*)d_in[4];  // [1024,3072]
    const float* b_attn = (const float*)d_in[5];  // [3072]
    const float* w_proj = (const float*)d_in[6];  // [1024,1024]
    const float* b_proj = (const float*)d_in[7];  // [1024]
    float*       out    = (float*)d_out;          // [32,1,1024]

    void* ap;
    cudaGetSymbolAddress(&ap, g_attn);

    // q partials: hs @ w_attn[:, :1024]
    gemm_part_kernel<<<dim3(16, KS_), 256>>>(hs, w_attn, 3072);

    // split-KV paged flash decode (q reduce + bias fused in prologue)
    attn_kernel<<<dim3(NH_, SPLITS, B_), 128>>>(kv, bt, sl, b_attn);

    // combine partials -> g_attn
    combine_kernel<<<128, 64>>>();

    // out = g_attn @ w_proj + b_proj
    gemm_part_kernel<<<dim3(16, KS_), 256>>>((const float*)ap, w_proj, 1024);
    gemm_reduce_kernel<<<128, 256>>>(b_proj, out);
}